// round 2
// baseline (speedup 1.0000x reference)
#include <cuda_runtime.h>
#include <math.h>

#define BATCH 64
#define Hh 512
#define Ww 512
#define NPIX (Hh * Ww)
#define NELEM (NPIX * 3)
#define MAGv 0.5f
#define ENHv (1.0f + 0.9f * MAGv)      // 1.45
#define FILLv 0.5f
#define INV_NELEM (1.0f / (float)NELEM)

__device__ float g_sumA[BATCH];   // sum of input image (for op0 == contrast)
__device__ float g_sumB[BATCH];   // sum of layer-0 output (for op1 == contrast)

struct L0P {
    int op;
    float A, Bc, TX, C, D, TY;   // affine inverse-map coeffs
    float f;                     // enhancement factor
    float m;                     // mean (contrast)
};

__device__ __forceinline__ float clip01(float v) {
    return fminf(fmaxf(v, 0.0f), 1.0f);
}

__device__ __forceinline__ void affineCoef(int op, float s,
        float& A, float& B, float& TX, float& C, float& D, float& TY) {
    A = 1.0f; B = 0.0f; TX = 0.0f; C = 0.0f; D = 1.0f; TY = 0.0f;
    if (op == 0) {                 // rotate: th = s * 15 deg
        float th = s * (30.0f * MAGv) * (3.14159265358979323846f / 180.0f);
        float si, co;
        sincosf(th, &si, &co);
        A = co; B = si; C = -si; D = co;
    } else if (op == 1) {          // shear_x
        B = -(s * 0.3f * MAGv);
    } else if (op == 2) {          // shear_y
        C = -(s * 0.3f * MAGv);
    } else if (op == 3) {          // trans_x
        TX = -(s * 0.3f * MAGv * (float)Ww);
    } else if (op == 4) {          // trans_y
        TY = -(s * 0.3f * MAGv * (float)Hh);
    }
}

// 3-channel gather with FILL outside bounds
__device__ __forceinline__ float3 tap3(const float* __restrict__ img, int yy, int xx) {
    if ((unsigned)xx >= (unsigned)Ww || (unsigned)yy >= (unsigned)Hh)
        return make_float3(FILLv, FILLv, FILLv);
    const float* p = img + (yy * Ww + xx) * 3;
    return make_float3(__ldg(p), __ldg(p + 1), __ldg(p + 2));
}

// Evaluate layer-0 output at in-bounds pixel (y, x). Exact reference semantics.
__device__ __forceinline__ float3 evalL0(const float* __restrict__ img, const L0P P,
                                         int y, int x) {
    if (P.op < 5) {
        // affine: inverse map about center, bilinear, FILL outside (no clip)
        const float cx = 255.5f, cy = 255.5f;
        float xi = P.A * ((float)x - cx) + P.Bc * ((float)y - cy) + P.TX + cx;
        float yi = P.C * ((float)x - cx) + P.D * ((float)y - cy) + P.TY + cy;
        float x0 = floorf(xi), y0 = floorf(yi);
        float wx = xi - x0, wy = yi - y0;
        int ix = (int)x0, iy = (int)y0;
        float w00 = (1.0f - wx) * (1.0f - wy);
        float w10 = wx * (1.0f - wy);
        float w01 = (1.0f - wx) * wy;
        float w11 = wx * wy;
        float3 v00 = tap3(img, iy, ix);
        float3 v10 = tap3(img, iy, ix + 1);
        float3 v01 = tap3(img, iy + 1, ix);
        float3 v11 = tap3(img, iy + 1, ix + 1);
        return make_float3(
            v00.x * w00 + v10.x * w10 + v01.x * w01 + v11.x * w11,
            v00.y * w00 + v10.y * w10 + v01.y * w01 + v11.y * w11,
            v00.z * w00 + v10.z * w10 + v01.z * w01 + v11.z * w11);
    } else if (P.op == 5) {        // brightness
        const float* p = img + (y * Ww + x) * 3;
        return make_float3(clip01(P.f * __ldg(p)),
                           clip01(P.f * __ldg(p + 1)),
                           clip01(P.f * __ldg(p + 2)));
    } else if (P.op == 6) {        // contrast
        const float* p = img + (y * Ww + x) * 3;
        return make_float3(clip01(P.m + P.f * (__ldg(p) - P.m)),
                           clip01(P.m + P.f * (__ldg(p + 1) - P.m)),
                           clip01(P.m + P.f * (__ldg(p + 2) - P.m)));
    } else {                       // sharpness: 3x3 edge-padded smooth blend
        float smr = 0.0f, smg = 0.0f, smb = 0.0f;
        #pragma unroll
        for (int dy = -1; dy <= 1; dy++) {
            int yc = min(max(y + dy, 0), Hh - 1);
            #pragma unroll
            for (int dx = -1; dx <= 1; dx++) {
                int xc = min(max(x + dx, 0), Ww - 1);
                float k = (dx == 0 && dy == 0) ? (5.0f / 13.0f) : (1.0f / 13.0f);
                const float* p = img + (yc * Ww + xc) * 3;
                smr += k * __ldg(p);
                smg += k * __ldg(p + 1);
                smb += k * __ldg(p + 2);
            }
        }
        const float* p = img + (y * Ww + x) * 3;
        float vr = __ldg(p), vg = __ldg(p + 1), vb = __ldg(p + 2);
        return make_float3(clip01(smr + P.f * (vr - smr)),
                           clip01(smg + P.f * (vg - smg)),
                           clip01(smb + P.f * (vb - smb)));
    }
}

__device__ __forceinline__ L0P makeL0P(const int* __restrict__ ops,
                                       const int* __restrict__ signs, int b) {
    L0P P;
    P.op = __ldg(&ops[b * 2]);
    float s0 = 2.0f * (float)__ldg(&signs[b * 2]) - 1.0f;
    affineCoef(P.op, s0, P.A, P.Bc, P.TX, P.C, P.D, P.TY);
    P.f = (s0 > 0.0f) ? ENHv : (1.0f / ENHv);
    P.m = g_sumA[b] * INV_NELEM;
    return P;
}

__global__ void zero_sums_kernel() {
    if (threadIdx.x < BATCH) {
        g_sumA[threadIdx.x] = 0.0f;
        g_sumB[threadIdx.x] = 0.0f;
    }
}

// Mean of the raw input, only for images with op0 == contrast. grid (64, BATCH)
__global__ void meanA_kernel(const float* __restrict__ in, const int* __restrict__ ops) {
    const int b = blockIdx.y;
    if (__ldg(&ops[b * 2]) != 6) return;
    const float* img = in + (size_t)b * NELEM;
    float acc = 0.0f;
    const int stride = gridDim.x * blockDim.x;
    for (int i = blockIdx.x * blockDim.x + threadIdx.x; i < NELEM; i += stride)
        acc += __ldg(&img[i]);
    __shared__ float sh[256];
    sh[threadIdx.x] = acc;
    __syncthreads();
    for (int off = 128; off > 0; off >>= 1) {
        if (threadIdx.x < off) sh[threadIdx.x] += sh[threadIdx.x + off];
        __syncthreads();
    }
    if (threadIdx.x == 0) atomicAdd(&g_sumA[b], sh[0]);
}

// Mean of the layer-0 output (recomputed, not materialized), for op1 == contrast.
__global__ void meanB_kernel(const float* __restrict__ in, const int* __restrict__ ops,
                             const int* __restrict__ signs) {
    const int b = blockIdx.y;
    if (__ldg(&ops[b * 2 + 1]) != 6) return;
    L0P P = makeL0P(ops, signs, b);
    const float* img = in + (size_t)b * NELEM;
    float acc = 0.0f;
    const int stride = gridDim.x * blockDim.x;
    for (int p = blockIdx.x * blockDim.x + threadIdx.x; p < NPIX; p += stride) {
        float3 v = evalL0(img, P, p >> 9, p & 511);
        acc += v.x + v.y + v.z;
    }
    __shared__ float sh[256];
    sh[threadIdx.x] = acc;
    __syncthreads();
    for (int off = 128; off > 0; off >>= 1) {
        if (threadIdx.x < off) sh[threadIdx.x] += sh[threadIdx.x + off];
        __syncthreads();
    }
    if (threadIdx.x == 0) atomicAdd(&g_sumB[b], sh[0]);
}

// Fused both-layer kernel. block (32, 8), grid (16, 64, BATCH). One thread = one pixel.
__global__ void fused_kernel(const float* __restrict__ in, float* __restrict__ out,
                             const int* __restrict__ ops, const int* __restrict__ signs) {
    const int b = blockIdx.z;
    const int tx = threadIdx.x, ty = threadIdx.y;
    const int x = blockIdx.x * 32 + tx;
    const int y = blockIdx.y * 8 + ty;

    L0P P = makeL0P(ops, signs, b);
    const int op1 = __ldg(&ops[b * 2 + 1]);
    const float s1 = 2.0f * (float)__ldg(&signs[b * 2 + 1]) - 1.0f;
    const float f1 = (s1 > 0.0f) ? ENHv : (1.0f / ENHv);

    const float* img = in + (size_t)b * NELEM;
    float* outb = out + (size_t)b * NELEM;

    float3 r;

    if (op1 < 5) {
        // outer affine over L0-image values (computed exactly per integer tap)
        float A, Bc, TX, C, D, TY;
        affineCoef(op1, s1, A, Bc, TX, C, D, TY);
        const float cx = 255.5f, cy = 255.5f;
        float xi = A * ((float)x - cx) + Bc * ((float)y - cy) + TX + cx;
        float yi = C * ((float)x - cx) + D * ((float)y - cy) + TY + cy;
        float x0 = floorf(xi), y0 = floorf(yi);
        float wx = xi - x0, wy = yi - y0;
        int ix = (int)x0, iy = (int)y0;
        float w[4] = { (1.0f - wx) * (1.0f - wy), wx * (1.0f - wy),
                       (1.0f - wx) * wy, wx * wy };
        int oy[4] = { iy, iy, iy + 1, iy + 1 };
        int ox[4] = { ix, ix + 1, ix, ix + 1 };
        r = make_float3(0.0f, 0.0f, 0.0f);
        #pragma unroll
        for (int t = 0; t < 4; t++) {
            float3 v;
            if ((unsigned)ox[t] >= (unsigned)Ww || (unsigned)oy[t] >= (unsigned)Hh)
                v = make_float3(FILLv, FILLv, FILLv);
            else
                v = evalL0(img, P, oy[t], ox[t]);
            r.x += w[t] * v.x;
            r.y += w[t] * v.y;
            r.z += w[t] * v.z;
        }
    } else if (op1 == 5) {            // brightness of L0
        float3 v = evalL0(img, P, y, x);
        r = make_float3(clip01(f1 * v.x), clip01(f1 * v.y), clip01(f1 * v.z));
    } else if (op1 == 6) {            // contrast of L0 (mean from prepass B)
        const float m1 = g_sumB[b] * INV_NELEM;
        float3 v = evalL0(img, P, y, x);
        r = make_float3(clip01(m1 + f1 * (v.x - m1)),
                        clip01(m1 + f1 * (v.y - m1)),
                        clip01(m1 + f1 * (v.z - m1)));
    } else {                          // sharpness of L0 via smem tile (34x10 with halo)
        __shared__ float sR[340], sG[340], sB[340];
        const int tid = ty * 32 + tx;
        const int tx0 = blockIdx.x * 32 - 1;
        const int ty0 = blockIdx.y * 8 - 1;
        for (int i = tid; i < 340; i += 256) {
            int hy = ty0 + i / 34;
            int hx = tx0 + (i - (i / 34) * 34);
            int yc = min(max(hy, 0), Hh - 1);
            int xc = min(max(hx, 0), Ww - 1);
            float3 v = evalL0(img, P, yc, xc);
            sR[i] = v.x; sG[i] = v.y; sB[i] = v.z;
        }
        __syncthreads();
        const int ci = (ty + 1) * 34 + (tx + 1);
        const float k1 = 1.0f / 13.0f, k5 = 5.0f / 13.0f;
        {
            float sm, c;
            sm = k1 * (sR[ci - 35] + sR[ci - 34] + sR[ci - 33] + sR[ci - 1] +
                       sR[ci + 1] + sR[ci + 33] + sR[ci + 34] + sR[ci + 35]) + k5 * sR[ci];
            c = sR[ci];
            r.x = clip01(sm + f1 * (c - sm));
            sm = k1 * (sG[ci - 35] + sG[ci - 34] + sG[ci - 33] + sG[ci - 1] +
                       sG[ci + 1] + sG[ci + 33] + sG[ci + 34] + sG[ci + 35]) + k5 * sG[ci];
            c = sG[ci];
            r.y = clip01(sm + f1 * (c - sm));
            sm = k1 * (sB[ci - 35] + sB[ci - 34] + sB[ci - 33] + sB[ci - 1] +
                       sB[ci + 1] + sB[ci + 33] + sB[ci + 34] + sB[ci + 35]) + k5 * sB[ci];
            c = sB[ci];
            r.z = clip01(sm + f1 * (c - sm));
        }
    }

    float* o = outb + (y * Ww + x) * 3;
    o[0] = r.x;
    o[1] = r.y;
    o[2] = r.z;
}

extern "C" void kernel_launch(void* const* d_in, const int* in_sizes, int n_in,
                              void* d_out, int out_size) {
    const float* images = (const float*)d_in[0];
    const int* op_ids = (const int*)d_in[1];
    const int* sgn = (const int*)d_in[2];
    float* out = (float*)d_out;

    zero_sums_kernel<<<1, 64>>>();
    meanA_kernel<<<dim3(64, BATCH), 256>>>(images, op_ids);
    meanB_kernel<<<dim3(64, BATCH), 256>>>(images, op_ids, sgn);
    fused_kernel<<<dim3(16, 64, BATCH), dim3(32, 8)>>>(images, out, op_ids, sgn);
}